// round 2
// baseline (speedup 1.0000x reference)
#include <cuda_runtime.h>
#include <cstdint>
#include <math.h>

// LSTM cell fused kernel: gates = [x|h0] @ [Wx|Wh]^T + b ; then elementwise.
// GEMM: M=8192 (batch), N=2048 per gate x 4 gates, K=4096 (2048 from x, 2048 from h0).
// tf32 mma.sync (m16n8k8), fp32 accumulate, fused sigmoid/tanh epilogue.

#define B_DIM 8192
#define H_DIM 2048
#define D_DIM 2048
#define K_TOT 4096

#define MT 128   // CTA M tile
#define NT 32    // CTA N tile (per gate; x4 gates computed by same CTA)
#define KT 32    // K tile
#define SPAD 36  // smem row stride in floats (144B, 16B aligned, conflict-friendly)

#define A_BUF_F (MT * SPAD)          // 4608 floats per A buffer
#define B_BUF_F (4 * NT * SPAD)      // 4608 floats per B buffer (4 gates)
#define B_BASE_F (2 * A_BUF_F)       // Bs starts after double-buffered As

__device__ __forceinline__ uint32_t f2tf32(float x) {
    uint32_t u;
    asm("cvt.rna.tf32.f32 %0, %1;" : "=r"(u) : "f"(x));
    return u;
}

__device__ __forceinline__ void mma_tf32(float* d, const uint32_t* a, const uint32_t* b) {
    asm volatile(
        "mma.sync.aligned.m16n8k8.row.col.f32.tf32.tf32.f32 "
        "{%0,%1,%2,%3},{%4,%5,%6,%7},{%8,%9},{%0,%1,%2,%3};"
        : "+f"(d[0]), "+f"(d[1]), "+f"(d[2]), "+f"(d[3])
        : "r"(a[0]), "r"(a[1]), "r"(a[2]), "r"(a[3]), "r"(b[0]), "r"(b[1]));
}

__device__ __forceinline__ void cp16(void* dst, const void* src) {
    uint32_t s = (uint32_t)__cvta_generic_to_shared(dst);
    asm volatile("cp.async.ca.shared.global [%0],[%1],16;" ::"r"(s), "l"(src));
}

extern __shared__ float smem[];

__global__ void __launch_bounds__(256, 1)
lstm_fused_tf32(
    const float* __restrict__ x, const float* __restrict__ h0, const float* __restrict__ c0,
    const float* __restrict__ Wx0, const float* __restrict__ Wx1,
    const float* __restrict__ Wx2, const float* __restrict__ Wx3,
    const float* __restrict__ Wh0, const float* __restrict__ Wh1,
    const float* __restrict__ Wh2, const float* __restrict__ Wh3,
    const float* __restrict__ bx0, const float* __restrict__ bx1,
    const float* __restrict__ bx2, const float* __restrict__ bx3,
    const float* __restrict__ bh0, const float* __restrict__ bh1,
    const float* __restrict__ bh2, const float* __restrict__ bh3,
    float* __restrict__ out_h, float* __restrict__ out_c)
{
    const int t = threadIdx.x;
    const int m_base = blockIdx.y * MT;
    const int n_base = blockIdx.x * NT;

    const float* Wx[4] = {Wx0, Wx1, Wx2, Wx3};
    const float* Wh[4] = {Wh0, Wh1, Wh2, Wh3};

    const int lrow = t >> 3;        // 0..31
    const int lc4  = (t & 7) * 4;   // 0,4,...,28

    // ---- tile loader (cp.async) ----
    auto load_tile = [&](int buf, int kt) {
        const int k0 = kt * KT;
        const bool first = (k0 < D_DIM);
        const float* Asrc = first ? x : h0;
        const int kofs = first ? k0 : (k0 - D_DIM);
        // A: 128 rows x 32 cols
        #pragma unroll
        for (int i = 0; i < 4; i++) {
            int r = i * 32 + lrow;
            cp16(&smem[buf * A_BUF_F + r * SPAD + lc4],
                 Asrc + (size_t)(m_base + r) * 2048 + kofs + lc4);
        }
        // B: 4 gates x 32 rows x 32 cols (weights are [N,K] row-major, K contiguous)
        #pragma unroll
        for (int g = 0; g < 4; g++) {
            const float* W = first ? Wx[g] : Wh[g];
            cp16(&smem[B_BASE_F + buf * B_BUF_F + g * (NT * SPAD) + lrow * SPAD + lc4],
                 W + (size_t)(n_base + lrow) * 2048 + kofs + lc4);
        }
        asm volatile("cp.async.commit_group;");
    };

    // ---- warp mapping ----
    const int warp = t >> 5;
    const int lane = t & 31;
    const int wm = warp & 3;    // 0..3  (M)
    const int wn = warp >> 2;   // 0..1  (N)
    const int gid = lane >> 2;  // 0..7
    const int tig = lane & 3;   // 0..3

    float acc[4][2][2][4];
    #pragma unroll
    for (int g = 0; g < 4; g++)
        #pragma unroll
        for (int mi = 0; mi < 2; mi++)
            #pragma unroll
            for (int ni = 0; ni < 2; ni++)
                #pragma unroll
                for (int e = 0; e < 4; e++) acc[g][mi][ni][e] = 0.f;

    const int NKT = K_TOT / KT;  // 128
    int buf = 0;
    load_tile(0, 0);

    for (int kt = 0; kt < NKT; kt++) {
        asm volatile("cp.async.wait_group 0;");
        __syncthreads();
        if (kt + 1 < NKT) load_tile(buf ^ 1, kt + 1);

        const float* As = &smem[buf * A_BUF_F];
        const float* Bs = &smem[B_BASE_F + buf * B_BUF_F];

        #pragma unroll
        for (int kk = 0; kk < KT / 8; kk++) {
            const int kb = kk * 8;
            uint32_t a[2][4];
            #pragma unroll
            for (int mi = 0; mi < 2; mi++) {
                const float* Ab = As + (wm * 32 + mi * 16 + gid) * SPAD + kb + tig;
                a[mi][0] = f2tf32(Ab[0]);
                a[mi][1] = f2tf32(Ab[8 * SPAD]);
                a[mi][2] = f2tf32(Ab[4]);
                a[mi][3] = f2tf32(Ab[8 * SPAD + 4]);
            }
            uint32_t bfr[4][2][2];
            #pragma unroll
            for (int g = 0; g < 4; g++) {
                #pragma unroll
                for (int ni = 0; ni < 2; ni++) {
                    const float* Bb = Bs + g * (NT * SPAD) + (wn * 16 + ni * 8 + gid) * SPAD + kb + tig;
                    bfr[g][ni][0] = f2tf32(Bb[0]);
                    bfr[g][ni][1] = f2tf32(Bb[4]);
                }
            }
            #pragma unroll
            for (int g = 0; g < 4; g++)
                #pragma unroll
                for (int mi = 0; mi < 2; mi++)
                    #pragma unroll
                    for (int ni = 0; ni < 2; ni++)
                        mma_tf32(acc[g][mi][ni], a[mi], bfr[g][ni]);
        }
        __syncthreads();
        buf ^= 1;
    }

    // ---- fused LSTM epilogue ----
    const int mrow = m_base + wm * 32;
    const int ncol = n_base + wn * 16;
    #pragma unroll
    for (int mi = 0; mi < 2; mi++) {
        #pragma unroll
        for (int ni = 0; ni < 2; ni++) {
            #pragma unroll
            for (int half = 0; half < 2; half++) {
                const int col = ncol + ni * 8 + tig * 2 + half;
                const float bi = __ldg(&bx0[col]) + __ldg(&bh0[col]);
                const float bf = __ldg(&bx1[col]) + __ldg(&bh1[col]);
                const float bg = __ldg(&bx2[col]) + __ldg(&bh2[col]);
                const float bo = __ldg(&bx3[col]) + __ldg(&bh3[col]);
                #pragma unroll
                for (int rh = 0; rh < 2; rh++) {
                    const int row = mrow + mi * 16 + gid + rh * 8;
                    const int e = rh * 2 + half;
                    const float gi = acc[0][mi][ni][e] + bi;
                    const float gf = acc[1][mi][ni][e] + bf;
                    const float gg = acc[2][mi][ni][e] + bg;
                    const float go = acc[3][mi][ni][e] + bo;
                    const float it = 1.f / (1.f + expf(-gi));
                    const float ft = 1.f / (1.f + expf(-gf));
                    const float gt = tanhf(gg);
                    const float ot = 1.f / (1.f + expf(-go));
                    const size_t off = (size_t)row * H_DIM + col;
                    const float cv = ft * __ldg(&c0[off]) + it * gt;
                    out_h[off] = ot * tanhf(cv);
                    out_c[off] = cv;
                }
            }
        }
    }
}

extern "C" void kernel_launch(void* const* d_in, const int* in_sizes, int n_in,
                              void* d_out, int out_size) {
    // setup_inputs() dict order:
    //   0:x 1:h0 2:c0
    //   3:W_ii 4:b_ii 5:W_if 6:b_if 7:W_ig 8:b_ig 9:W_io 10:b_io
    //   11:W_hi 12:b_hi 13:W_hf 14:b_hf 15:W_hg 16:b_hg 17:W_ho 18:b_ho
    const float* x  = (const float*)d_in[0];
    const float* h0 = (const float*)d_in[1];
    const float* c0 = (const float*)d_in[2];
    const float* W_ii = (const float*)d_in[3];  const float* b_ii = (const float*)d_in[4];
    const float* W_if = (const float*)d_in[5];  const float* b_if = (const float*)d_in[6];
    const float* W_ig = (const float*)d_in[7];  const float* b_ig = (const float*)d_in[8];
    const float* W_io = (const float*)d_in[9];  const float* b_io = (const float*)d_in[10];
    const float* W_hi = (const float*)d_in[11]; const float* b_hi = (const float*)d_in[12];
    const float* W_hf = (const float*)d_in[13]; const float* b_hf = (const float*)d_in[14];
    const float* W_hg = (const float*)d_in[15]; const float* b_hg = (const float*)d_in[16];
    const float* W_ho = (const float*)d_in[17]; const float* b_ho = (const float*)d_in[18];

    float* out_h = (float*)d_out;
    float* out_c = out_h + (size_t)B_DIM * H_DIM;

    const int smem_bytes = (2 * A_BUF_F + 2 * B_BUF_F) * sizeof(float);  // 73728
    cudaFuncSetAttribute(lstm_fused_tf32, cudaFuncAttributeMaxDynamicSharedMemorySize, smem_bytes);

    dim3 grid(H_DIM / NT, B_DIM / MT);  // (64, 64)
    dim3 block(256);
    lstm_fused_tf32<<<grid, block, smem_bytes>>>(
        x, h0, c0,
        W_ii, W_if, W_ig, W_io,
        W_hi, W_hf, W_hg, W_ho,
        b_ii, b_if, b_ig, b_io,
        b_hi, b_hf, b_hg, b_ho,
        out_h, out_c);
}

// round 4
// speedup vs baseline: 2.1640x; 2.1640x over previous
#include <cuda_runtime.h>
#include <cstdint>
#include <math.h>

// LSTM cell: gates = [x|h0] @ [Wx|Wh]^T + b, fused elementwise epilogue.
// Dual-path: tcgen05 tf32 SS GEMM (sm_103a feature pass) with runtime
// fallback to a legacy mma.sync tf32 kernel if the loaded cubin is the
// non-'a' pass (tcgen05 body compiles to an empty stub there).

#define BATCH 8192
#define HID   2048
#define KTOT  4096

#if defined(__CUDA_ARCH__) && defined(__CUDA_ARCH_FEAT_SM103_ALL)
#define HAS_TCGEN05 1
#else
#define HAS_TCGEN05 0
#endif

// ================== shared helpers ==================
__device__ __forceinline__ uint32_t f2tf32(float x) {
    uint32_t u; asm("cvt.rna.tf32.f32 %0, %1;" : "=r"(u) : "f"(x)); return u;
}

// -------- scratch for tcgen05 path (module-load allocated) --------
__device__ float g_A[(size_t)BATCH * KTOT];      // 134 MB: [x|h0], tf32-rounded
__device__ float g_W[(size_t)4 * HID * KTOT];    // 134 MB: [Wx|Wh] per gate

// ============================ pack kernels ============================
__global__ void pack_a(const float* __restrict__ x, const float* __restrict__ h0) {
    const size_t n4 = (size_t)BATCH * KTOT / 4;
    for (size_t i = (size_t)blockIdx.x * blockDim.x + threadIdx.x; i < n4;
         i += (size_t)gridDim.x * blockDim.x) {
        size_t idx = i * 4;
        size_t row = idx >> 12;
        int k = (int)(idx & 4095);
        const float* src = (k < 2048) ? (x + row * 2048 + k) : (h0 + row * 2048 + (k - 2048));
        float4 v = *(const float4*)src;
        v.x = __uint_as_float(f2tf32(v.x));
        v.y = __uint_as_float(f2tf32(v.y));
        v.z = __uint_as_float(f2tf32(v.z));
        v.w = __uint_as_float(f2tf32(v.w));
        *(float4*)(g_A + idx) = v;
    }
}

__global__ void pack_w(const float* __restrict__ Wii, const float* __restrict__ Wif,
                       const float* __restrict__ Wig, const float* __restrict__ Wio,
                       const float* __restrict__ Whi, const float* __restrict__ Whf,
                       const float* __restrict__ Whg, const float* __restrict__ Who) {
    const float* Wi[4] = {Wii, Wif, Wig, Wio};
    const float* Wh[4] = {Whi, Whf, Whg, Who};
    const size_t n4 = (size_t)4 * HID * KTOT / 4;
    for (size_t i = (size_t)blockIdx.x * blockDim.x + threadIdx.x; i < n4;
         i += (size_t)gridDim.x * blockDim.x) {
        size_t idx = i * 4;
        size_t row = idx >> 12;           // gate*2048 + hcol
        int k = (int)(idx & 4095);
        int gate = (int)(row >> 11);
        size_t h = row & 2047;
        const float* src = (k < 2048) ? (Wi[gate] + h * 2048 + k)
                                      : (Wh[gate] + h * 2048 + (k - 2048));
        float4 v = *(const float4*)src;
        v.x = __uint_as_float(f2tf32(v.x));
        v.y = __uint_as_float(f2tf32(v.y));
        v.z = __uint_as_float(f2tf32(v.z));
        v.w = __uint_as_float(f2tf32(v.w));
        *(float4*)(g_W + idx) = v;
    }
}

// ======================================================================
// tcgen05 path (only real on the sm_103a feature pass)
// ======================================================================
#define MT 128      // CTA M tile
#define NTT 256     // CTA N tile = 4 gates x 64 h-cols
#define KT 32       // K per stage (32 tf32 = 128B rows, SW128 native)
#define STAGES 4
#define STAGE_BYTES (MT*128 + NTT*128)   // 48KB
#define A_STAGE_BYTES (MT*128)
#define NPROD 256
#define TC_SMEM_BYTES (2048 + STAGES * STAGE_BYTES)

#if HAS_TCGEN05
__device__ __forceinline__ uint32_t smem_u32(const void* p) {
    uint32_t a;
    asm("{ .reg .u64 t; cvta.to.shared.u64 t, %1; cvt.u32.u64 %0, t; }" : "=r"(a) : "l"(p));
    return a;
}
__device__ __forceinline__ uint32_t elect_one() {
    uint32_t p;
    asm volatile("{\n\t.reg .pred P;\n\telect.sync _|P, 0xFFFFFFFF;\n\tselp.b32 %0, 1, 0, P;\n\t}" : "=r"(p));
    return p;
}
#define MBAR_INIT(addr, cnt) \
    asm volatile("mbarrier.init.shared.b64 [%0], %1;" :: "r"(addr), "r"(cnt) : "memory")
#define MBAR_WAIT(addr, par) do { \
    uint32_t _m = (addr); uint32_t _p = (par); uint32_t _d; \
    asm volatile("{\n\t.reg .pred p;\n\tmbarrier.try_wait.parity.acquire.cta.shared::cta.b64 p, [%1], %2;\n\tselp.b32 %0, 1, 0, p;\n\t}" \
        : "=r"(_d) : "r"(_m), "r"(_p) : "memory"); \
    if (!_d) { \
        asm volatile("{\n\t.reg .pred P1;\n\tWL_%=:\n\tmbarrier.try_wait.parity.acquire.cta.shared::cta.b64 P1, [%0], %1, 0x989680;\n\t@P1 bra.uni WD_%=;\n\tbra.uni WL_%=;\n\tWD_%=:\n\t}" \
            :: "r"(_m), "r"(_p) : "memory"); \
    } } while (0)
#define TC_ALLOC(smem_addr, n) \
    asm volatile("tcgen05.alloc.cta_group::1.sync.aligned.shared::cta.b32 [%0], %1;" :: "r"(smem_addr), "r"(n) : "memory")
#define TC_DEALLOC(tmem, n) \
    asm volatile("tcgen05.dealloc.cta_group::1.sync.aligned.b32 %0, %1;" :: "r"(tmem), "r"(n))
#define TC_RELINQ() asm volatile("tcgen05.relinquish_alloc_permit.cta_group::1.sync.aligned;")
#define TC_COMMIT(mbar) \
    asm volatile("tcgen05.commit.cta_group::1.mbarrier::arrive::one.shared::cluster.b64 [%0];" :: "r"(mbar) : "memory")
#define TC_FENCE_AFTER()  asm volatile("tcgen05.fence::after_thread_sync;" ::: "memory")
#define TC_WAIT_LD()      asm volatile("tcgen05.wait::ld.sync.aligned;" ::: "memory")

__device__ __forceinline__ void mma_tf32_ss(uint32_t d, uint64_t a, uint64_t b,
                                            uint32_t idesc, uint32_t en) {
    asm volatile(
        "{\n\t.reg .pred p;\n\tsetp.ne.u32 p, %4, 0;\n\t"
        "tcgen05.mma.cta_group::1.kind::tf32 [%0], %1, %2, %3, p;\n\t}"
        :: "r"(d), "l"(a), "l"(b), "r"(idesc), "r"(en) : "memory");
}
#define LDTM_X16(r, addr) \
    asm volatile("tcgen05.ld.sync.aligned.32x32b.x16.b32 " \
        "{%0,%1,%2,%3,%4,%5,%6,%7,%8,%9,%10,%11,%12,%13,%14,%15}, [%16];" \
        : "=r"((r)[0]), "=r"((r)[1]), "=r"((r)[2]), "=r"((r)[3]), \
          "=r"((r)[4]), "=r"((r)[5]), "=r"((r)[6]), "=r"((r)[7]), \
          "=r"((r)[8]), "=r"((r)[9]), "=r"((r)[10]), "=r"((r)[11]), \
          "=r"((r)[12]), "=r"((r)[13]), "=r"((r)[14]), "=r"((r)[15]) \
        : "r"(addr))

__device__ __forceinline__ void cp16g(uint32_t dst, const void* src) {
    asm volatile("cp.async.cg.shared.global [%0], [%1], 16;" :: "r"(dst), "l"(src) : "memory");
}
__device__ __forceinline__ void cp_arrive(uint32_t mbar) {
    asm volatile("cp.async.mbarrier.arrive.noinc.shared::cta.b64 [%0];" :: "r"(mbar) : "memory");
}
__device__ __forceinline__ uint32_t swz(uint32_t off) { return off ^ ((off >> 3) & 0x70); }
__device__ __forceinline__ uint64_t make_desc(uint32_t addr) {
    return (uint64_t(2) << 61) | (uint64_t(1) << 46) | (uint64_t(64) << 32)
         | (uint64_t(1) << 16) | ((uint64_t)(addr >> 4) & 0x3FFF);
}
// idesc: dtype=F32(1<<4), atype=TF32(2<<7), btype=TF32(2<<10), N=256, M=128
#define IDESC ((1u<<4) | (2u<<7) | (2u<<10) | ((NTT/8)<<17) | ((MT/16)<<24))
#endif // HAS_TCGEN05

extern __shared__ char dsmem[];

__global__ void __launch_bounds__(288, 1)
lstm_tc(const float* __restrict__ c0,
        const float* __restrict__ bii, const float* __restrict__ bif,
        const float* __restrict__ big, const float* __restrict__ bio,
        const float* __restrict__ bhi, const float* __restrict__ bhf,
        const float* __restrict__ bhg, const float* __restrict__ bho,
        float* __restrict__ out_h, float* __restrict__ out_c)
{
#if HAS_TCGEN05
    const uint32_t sb = smem_u32(dsmem);
    const uint32_t full0  = sb;        // 4 mbarriers
    const uint32_t empty0 = sb + 64;   // 4 mbarriers
    const uint32_t doneb  = sb + 128;  // final-MMA barrier
    const uint32_t tptr   = sb + 192;
    const uint32_t tiles  = (sb + 1024 + 1023) & ~1023u;

    const int tid = threadIdx.x;
    const int warp = tid >> 5;
    const int lane = tid & 31;
    const int m0  = blockIdx.y * MT;
    const int nh0 = blockIdx.x * 64;

    if (tid == 0) {
        #pragma unroll
        for (int s = 0; s < STAGES; s++) {
            MBAR_INIT(full0 + s * 8, NPROD);
            MBAR_INIT(empty0 + s * 8, 1);
        }
        MBAR_INIT(doneb, 1);
    }
    if (warp == 8) TC_ALLOC(tptr, 256);
    __syncthreads();

    uint32_t tmem;
    asm volatile("ld.shared.b32 %0, [%1];" : "=r"(tmem) : "r"(tptr));

    const int NKT = KTOT / KT;  // 128

    if (warp == 8) {
        // ---------------- MMA warp ----------------
        uint64_t ad[STAGES], bd[STAGES];
        #pragma unroll
        for (int s = 0; s < STAGES; s++) {
            ad[s] = make_desc(tiles + s * STAGE_BYTES);
            bd[s] = make_desc(tiles + s * STAGE_BYTES + A_STAGE_BYTES);
        }
        int ph[STAGES] = {0, 0, 0, 0};
        for (int kt = 0; kt < NKT; kt++) {
            const int s = kt & 3;
            MBAR_WAIT(full0 + s * 8, ph[s]); ph[s] ^= 1;
            if (elect_one()) {
                #pragma unroll
                for (int k = 0; k < KT / 8; k++)
                    mma_tf32_ss(tmem, ad[s] + k * 2, bd[s] + k * 2, IDESC,
                                (kt > 0 || k > 0) ? 1u : 0u);
                // last iteration signals `done` (producers never re-wait empty[3]
                // after their final refill); others signal pipeline empty[s].
                TC_COMMIT((kt == NKT - 1) ? doneb : (empty0 + s * 8));
            }
        }
    } else {
        // ---------------- producer warps 0-7 ----------------
        const float* srcp[12];
        uint32_t dsto[12];
        #pragma unroll
        for (int i = 0; i < 12; i++) {
            int c = tid + i * NPROD;            // 0..3071
            if (c < 1024) {                     // A chunk: 128 rows x 8 x 16B
                int row = c >> 3, kc = c & 7;
                srcp[i] = g_A + (size_t)(m0 + row) * KTOT + kc * 4;
                dsto[i] = swz((uint32_t)(row * 128 + kc * 16));
            } else {                            // B chunk: 256 rows x 8 x 16B
                int cb = c - 1024;
                int row = cb >> 3, kc = cb & 7; // row = gate*64 + hcol
                int gate = row >> 6, hc = row & 63;
                srcp[i] = g_W + (size_t)(gate * HID + nh0 + hc) * KTOT + kc * 4;
                dsto[i] = (uint32_t)A_STAGE_BYTES + swz((uint32_t)(row * 128 + kc * 16));
            }
        }
        int eph[STAGES] = {0, 0, 0, 0};
        for (int kl = 0; kl < NKT; kl++) {
            const int s = kl & 3;
            if (kl >= STAGES) { MBAR_WAIT(empty0 + s * 8, eph[s]); eph[s] ^= 1; }
            const uint32_t base = tiles + s * STAGE_BYTES;
            #pragma unroll
            for (int i = 0; i < 12; i++) cp16g(base + dsto[i], srcp[i]);
            cp_arrive(full0 + s * 8);
            #pragma unroll
            for (int i = 0; i < 12; i++) srcp[i] += KT;
        }
    }

    // ---------------- epilogue: warps 0-3 ----------------
    if (warp < 4) {
        MBAR_WAIT(doneb, 0);
        TC_FENCE_AFTER();

        const int row = m0 + warp * 32 + lane;
        const size_t rb = (size_t)row * HID + nh0;

        #pragma unroll
        for (int jc = 0; jc < 4; jc++) {
            uint32_t ri[16], rf[16], rg[16], ro[16];
            LDTM_X16(ri, tmem + 0   + jc * 16);
            LDTM_X16(rf, tmem + 64  + jc * 16);
            LDTM_X16(rg, tmem + 128 + jc * 16);
            LDTM_X16(ro, tmem + 192 + jc * 16);
            TC_WAIT_LD();
            #pragma unroll
            for (int e = 0; e < 16; e++) {
                const int col = nh0 + jc * 16 + e;
                const float gi = __uint_as_float(ri[e]) + __ldg(&bii[col]) + __ldg(&bhi[col]);
                const float gf = __uint_as_float(rf[e]) + __ldg(&bif[col]) + __ldg(&bhf[col]);
                const float gg = __uint_as_float(rg[e]) + __ldg(&big[col]) + __ldg(&bhg[col]);
                const float go = __uint_as_float(ro[e]) + __ldg(&bio[col]) + __ldg(&bho[col]);
                const float it = 1.f / (1.f + expf(-gi));
                const float ft = 1.f / (1.f + expf(-gf));
                const float gt = tanhf(gg);
                const float ot = 1.f / (1.f + expf(-go));
                const float cv = ft * __ldg(&c0[rb + jc * 16 + e]) + it * gt;
                out_h[rb + jc * 16 + e] = ot * tanhf(cv);
                out_c[rb + jc * 16 + e] = cv;
            }
        }
    }

    __syncthreads();
    if (warp == 8) {
        TC_RELINQ();
        TC_DEALLOC(tmem, 256);
    }
#endif // HAS_TCGEN05
}

// ======================================================================
// Fallback: legacy mma.sync tf32 kernel (known-good, 3413us)
// ======================================================================
#define FMT 128
#define FNT 32
#define FKT 32
#define SPAD 36
#define A_BUF_F (FMT * SPAD)
#define B_BUF_F (4 * FNT * SPAD)
#define B_BASE_F (2 * A_BUF_F)
#define FB_SMEM_BYTES ((2 * A_BUF_F + 2 * B_BUF_F) * (int)sizeof(float))

__device__ __forceinline__ void mma_tf32(float* d, const uint32_t* a, const uint32_t* b) {
    asm volatile(
        "mma.sync.aligned.m16n8k8.row.col.f32.tf32.tf32.f32 "
        "{%0,%1,%2,%3},{%4,%5,%6,%7},{%8,%9},{%0,%1,%2,%3};"
        : "+f"(d[0]), "+f"(d[1]), "+f"(d[2]), "+f"(d[3])
        : "r"(a[0]), "r"(a[1]), "r"(a[2]), "r"(a[3]), "r"(b[0]), "r"(b[1]));
}
__device__ __forceinline__ void cp16f(void* dst, const void* src) {
    uint32_t s = (uint32_t)__cvta_generic_to_shared(dst);
    asm volatile("cp.async.ca.shared.global [%0],[%1],16;" ::"r"(s), "l"(src));
}

__global__ void __launch_bounds__(256, 1)
lstm_fused_tf32(
    const float* __restrict__ x, const float* __restrict__ h0, const float* __restrict__ c0,
    const float* __restrict__ Wx0, const float* __restrict__ Wx1,
    const float* __restrict__ Wx2, const float* __restrict__ Wx3,
    const float* __restrict__ Wh0, const float* __restrict__ Wh1,
    const float* __restrict__ Wh2, const float* __restrict__ Wh3,
    const float* __restrict__ bx0, const float* __restrict__ bx1,
    const float* __restrict__ bx2, const float* __restrict__ bx3,
    const float* __restrict__ bh0, const float* __restrict__ bh1,
    const float* __restrict__ bh2, const float* __restrict__ bh3,
    float* __restrict__ out_h, float* __restrict__ out_c)
{
    float* smem = (float*)dsmem;
    const int t = threadIdx.x;
    const int m_base = blockIdx.y * FMT;
    const int n_base = blockIdx.x * FNT;

    const float* Wx[4] = {Wx0, Wx1, Wx2, Wx3};
    const float* Wh[4] = {Wh0, Wh1, Wh2, Wh3};

    const int lrow = t >> 3;
    const int lc4  = (t & 7) * 4;

    auto load_tile = [&](int buf, int kt) {
        const int k0 = kt * FKT;
        const bool first = (k0 < 2048);
        const float* Asrc = first ? x : h0;
        const int kofs = first ? k0 : (k0 - 2048);
        #pragma unroll
        for (int i = 0; i < 4; i++) {
            int r = i * 32 + lrow;
            cp16f(&smem[buf * A_BUF_F + r * SPAD + lc4],
                  Asrc + (size_t)(m_base + r) * 2048 + kofs + lc4);
        }
        #pragma unroll
        for (int g = 0; g < 4; g++) {
            const float* W = first ? Wx[g] : Wh[g];
            cp16f(&smem[B_BASE_F + buf * B_BUF_F + g * (FNT * SPAD) + lrow * SPAD + lc4],
                  W + (size_t)(n_base + lrow) * 2048 + kofs + lc4);
        }
        asm volatile("cp.async.commit_group;");
    };

    const int warp = t >> 5;
    const int lane = t & 31;
    const int wm = warp & 3;
    const int wn = warp >> 2;
    const int gid = lane >> 2;
    const int tig = lane & 3;

    float acc[4][2][2][4];
    #pragma unroll
    for (int g = 0; g < 4; g++)
        #pragma unroll
        for (int mi = 0; mi < 2; mi++)
            #pragma unroll
            for (int ni = 0; ni < 2; ni++)
                #pragma unroll
                for (int e = 0; e < 4; e++) acc[g][mi][ni][e] = 0.f;

    const int NKT = KTOT / FKT;
    int buf = 0;
    load_tile(0, 0);

    for (int kt = 0; kt < NKT; kt++) {
        asm volatile("cp.async.wait_group 0;");
        __syncthreads();
        if (kt + 1 < NKT) load_tile(buf ^ 1, kt + 1);

        const float* As = &smem[buf * A_BUF_F];
        const float* Bs = &smem[B_BASE_F + buf * B_BUF_F];

        #pragma unroll
        for (int kk = 0; kk < FKT / 8; kk++) {
            const int kb = kk * 8;
            uint32_t a[2][4];
            #pragma unroll
            for (int mi = 0; mi < 2; mi++) {
                const float* Ab = As + (wm * 32 + mi * 16 + gid) * SPAD + kb + tig;
                a[mi][0] = f2tf32(Ab[0]);
                a[mi][1] = f2tf32(Ab[8 * SPAD]);
                a[mi][2] = f2tf32(Ab[4]);
                a[mi][3] = f2tf32(Ab[8 * SPAD + 4]);
            }
            uint32_t bfr[4][2][2];
            #pragma unroll
            for (int g = 0; g < 4; g++) {
                #pragma unroll
                for (int ni = 0; ni < 2; ni++) {
                    const float* Bb = Bs + g * (FNT * SPAD) + (wn * 16 + ni * 8 + gid) * SPAD + kb + tig;
                    bfr[g][ni][0] = f2tf32(Bb[0]);
                    bfr[g][ni][1] = f2tf32(Bb[4]);
                }
            }
            #pragma unroll
            for (int g = 0; g < 4; g++)
                #pragma unroll
                for (int mi = 0; mi < 2; mi++)
                    #pragma unroll
                    for (int ni = 0; ni < 2; ni++)
                        mma_tf32(acc[g][mi][ni], a[mi], bfr[g][ni]);
        }
        __syncthreads();
        buf ^= 1;
    }

    const int mrow = m_base + wm * 32;
    const int ncol = n_base + wn * 16;
    #pragma unroll
    for (int mi = 0; mi < 2; mi++) {
        #pragma unroll
        for (int ni = 0; ni < 2; ni++) {
            #pragma unroll
            for (int half = 0; half < 2; half++) {
                const int col = ncol + ni * 8 + tig * 2 + half;
                const float bi = __ldg(&bx0[col]) + __ldg(&bh0[col]);
                const float bf = __ldg(&bx1[col]) + __ldg(&bh1[col]);
                const float bg = __ldg(&bx2[col]) + __ldg(&bh2[col]);
                const float bo = __ldg(&bx3[col]) + __ldg(&bh3[col]);
                #pragma unroll
                for (int rh = 0; rh < 2; rh++) {
                    const int row = mrow + mi * 16 + gid + rh * 8;
                    const int e = rh * 2 + half;
                    const float gi = acc[0][mi][ni][e] + bi;
                    const float gf = acc[1][mi][ni][e] + bf;
                    const float gg = acc[2][mi][ni][e] + bg;
                    const float go = acc[3][mi][ni][e] + bo;
                    const float it = 1.f / (1.f + expf(-gi));
                    const float ft = 1.f / (1.f + expf(-gf));
                    const float gt = tanhf(gg);
                    const float ot = 1.f / (1.f + expf(-go));
                    const size_t off = (size_t)row * HID + col;
                    const float cv = ft * __ldg(&c0[off]) + it * gt;
                    out_h[off] = ot * tanhf(cv);
                    out_c[off] = cv;
                }
            }
        }
    }
}

// ============================ launch ============================
extern "C" void kernel_launch(void* const* d_in, const int* in_sizes, int n_in,
                              void* d_out, int out_size) {
    const float* x   = (const float*)d_in[0];
    const float* h0  = (const float*)d_in[1];
    const float* c0  = (const float*)d_in[2];
    const float* Wii = (const float*)d_in[3];  const float* bii = (const float*)d_in[4];
    const float* Wif = (const float*)d_in[5];  const float* bif = (const float*)d_in[6];
    const float* Wig = (const float*)d_in[7];  const float* big = (const float*)d_in[8];
    const float* Wio = (const float*)d_in[9];  const float* bio = (const float*)d_in[10];
    const float* Whi = (const float*)d_in[11]; const float* bhi = (const float*)d_in[12];
    const float* Whf = (const float*)d_in[13]; const float* bhf = (const float*)d_in[14];
    const float* Whg = (const float*)d_in[15]; const float* bhg = (const float*)d_in[16];
    const float* Who = (const float*)d_in[17]; const float* bho = (const float*)d_in[18];

    float* out_h = (float*)d_out;
    float* out_c = out_h + (size_t)BATCH * HID;

    // Probe which cubin variant got loaded: the tcgen05 kernel is an empty
    // stub on the non-'a' pass (tiny register count).
    static int use_tc = -1;
    if (use_tc < 0) {
        cudaFuncAttributes attr;
        use_tc = 0;
        if (cudaFuncGetAttributes(&attr, lstm_tc) == cudaSuccess && attr.numRegs > 32)
            use_tc = 1;
        if (use_tc) {
            cudaFuncSetAttribute(lstm_tc, cudaFuncAttributeMaxDynamicSharedMemorySize,
                                 TC_SMEM_BYTES);
        } else {
            cudaFuncSetAttribute(lstm_fused_tf32,
                                 cudaFuncAttributeMaxDynamicSharedMemorySize, FB_SMEM_BYTES);
        }
    }

    if (use_tc) {
        pack_a<<<4096, 256>>>(x, h0);
        pack_w<<<4096, 256>>>(Wii, Wif, Wig, Wio, Whi, Whf, Whg, Who);
        dim3 grid(HID / 64, BATCH / MT);   // (32, 64)
        lstm_tc<<<grid, 288, TC_SMEM_BYTES>>>(c0,
            bii, bif, big, bio, bhi, bhf, bhg, bho, out_h, out_c);
    } else {
        dim3 grid(HID / FNT, BATCH / FMT); // (64, 64)
        lstm_fused_tf32<<<grid, 256, FB_SMEM_BYTES>>>(
            x, h0, c0,
            Wii, Wif, Wig, Wio,
            Whi, Whf, Whg, Who,
            bii, bif, big, bio,
            bhi, bhf, bhg, bho,
            out_h, out_c);
    }
}

// round 5
// speedup vs baseline: 3.0883x; 1.4271x over previous
#include <cuda_runtime.h>
#include <cuda.h>
#include <cstdint>
#include <math.h>

// LSTM cell: gates = [x|h0] @ [Wx|Wh]^T + b, fused elementwise epilogue.
// R5: tcgen05 tf32 SS GEMM, 256x256 CTA tile (2 MMA dispatches, 512 TMEM cols),
// TMA bulk loads (SW128 tensormaps) replacing cp.async producers.
// Fallback to legacy mma.sync kernel if the 'a'-pass cubin / tensormap
// encode is unavailable.

#define BATCH 8192
#define HID   2048
#define KTOT  4096

#if defined(__CUDA_ARCH__) && defined(__CUDA_ARCH_FEAT_SM103_ALL)
#define HAS_TCGEN05 1
#else
#define HAS_TCGEN05 0
#endif

__device__ __forceinline__ uint32_t f2tf32(float x) {
    uint32_t u; asm("cvt.rna.tf32.f32 %0, %1;" : "=r"(u) : "f"(x)); return u;
}

// -------- scratch (module-load allocated) --------
__device__ float g_A[(size_t)BATCH * KTOT];      // [x|h0], tf32-rounded, [8192,4096]
__device__ float g_W[(size_t)4 * HID * KTOT];    // reordered weights, [8192,4096]

// ============================ pack kernels ============================
__global__ void pack_a(const float* __restrict__ x, const float* __restrict__ h0) {
    const size_t n4 = (size_t)BATCH * KTOT / 4;
    for (size_t i = (size_t)blockIdx.x * blockDim.x + threadIdx.x; i < n4;
         i += (size_t)gridDim.x * blockDim.x) {
        size_t idx = i * 4;
        size_t row = idx >> 12;
        int k = (int)(idx & 4095);
        const float* src = (k < 2048) ? (x + row * 2048 + k) : (h0 + row * 2048 + (k - 2048));
        float4 v = *(const float4*)src;
        v.x = __uint_as_float(f2tf32(v.x));
        v.y = __uint_as_float(f2tf32(v.y));
        v.z = __uint_as_float(f2tf32(v.z));
        v.w = __uint_as_float(f2tf32(v.w));
        *(float4*)(g_A + idx) = v;
    }
}

// g_W row r = nblk*256 + gate*64 + hc  (so each CTA's 256 B-rows are contiguous)
__global__ void pack_w(const float* __restrict__ Wii, const float* __restrict__ Wif,
                       const float* __restrict__ Wig, const float* __restrict__ Wio,
                       const float* __restrict__ Whi, const float* __restrict__ Whf,
                       const float* __restrict__ Whg, const float* __restrict__ Who) {
    const float* Wi[4] = {Wii, Wif, Wig, Wio};
    const float* Wh[4] = {Whi, Whf, Whg, Who};
    const size_t n4 = (size_t)4 * HID * KTOT / 4;
    for (size_t i = (size_t)blockIdx.x * blockDim.x + threadIdx.x; i < n4;
         i += (size_t)gridDim.x * blockDim.x) {
        size_t idx = i * 4;
        size_t row = idx >> 12;            // 0..8191
        int k = (int)(idx & 4095);
        int gate = (int)((row >> 6) & 3);
        size_t h = (row >> 8) * 64 + (row & 63);
        const float* src = (k < 2048) ? (Wi[gate] + h * 2048 + k)
                                      : (Wh[gate] + h * 2048 + (k - 2048));
        float4 v = *(const float4*)src;
        v.x = __uint_as_float(f2tf32(v.x));
        v.y = __uint_as_float(f2tf32(v.y));
        v.z = __uint_as_float(f2tf32(v.z));
        v.w = __uint_as_float(f2tf32(v.w));
        *(float4*)(g_W + idx) = v;
    }
}

// ======================================================================
// tcgen05 + TMA path
// ======================================================================
#define MT2 256      // CTA M tile (2 x 128 dispatches)
#define NTT 256      // CTA N tile = 4 gates x 64 h-cols
#define KT 32        // K per stage (128B rows, SW128 native)
#define STAGES 3
#define A_STG 32768                 // 256 rows x 128B
#define B_STG 32768
#define STAGE_BYTES (A_STG + B_STG) // 64KB
#define TC_SMEM_BYTES (2048 + STAGES * STAGE_BYTES)   // 198656

#if HAS_TCGEN05
__device__ __forceinline__ uint32_t smem_u32(const void* p) {
    uint32_t a;
    asm("{ .reg .u64 t; cvta.to.shared.u64 t, %1; cvt.u32.u64 %0, t; }" : "=r"(a) : "l"(p));
    return a;
}
#define MBAR_INIT(addr, cnt) \
    asm volatile("mbarrier.init.shared.b64 [%0], %1;" :: "r"(addr), "r"(cnt) : "memory")
#define MBAR_EXPECT_TX(addr, bytes) \
    asm volatile("mbarrier.arrive.expect_tx.shared.b64 _, [%0], %1;" :: "r"(addr), "r"(bytes) : "memory")
#define MBAR_WAIT(addr, par) do { \
    uint32_t _m = (addr); uint32_t _p = (par); uint32_t _d; \
    asm volatile("{\n\t.reg .pred p;\n\tmbarrier.try_wait.parity.acquire.cta.shared::cta.b64 p, [%1], %2;\n\tselp.b32 %0, 1, 0, p;\n\t}" \
        : "=r"(_d) : "r"(_m), "r"(_p) : "memory"); \
    if (!_d) { \
        asm volatile("{\n\t.reg .pred P1;\n\tWL_%=:\n\tmbarrier.try_wait.parity.acquire.cta.shared::cta.b64 P1, [%0], %1, 0x989680;\n\t@P1 bra.uni WD_%=;\n\tbra.uni WL_%=;\n\tWD_%=:\n\t}" \
            :: "r"(_m), "r"(_p) : "memory"); \
    } } while (0)
#define TC_ALLOC(smem_addr, n) \
    asm volatile("tcgen05.alloc.cta_group::1.sync.aligned.shared::cta.b32 [%0], %1;" :: "r"(smem_addr), "r"(n) : "memory")
#define TC_DEALLOC(tmem, n) \
    asm volatile("tcgen05.dealloc.cta_group::1.sync.aligned.b32 %0, %1;" :: "r"(tmem), "r"(n))
#define TC_RELINQ() asm volatile("tcgen05.relinquish_alloc_permit.cta_group::1.sync.aligned;")
#define TC_COMMIT(mbar) \
    asm volatile("tcgen05.commit.cta_group::1.mbarrier::arrive::one.shared::cluster.b64 [%0];" :: "r"(mbar) : "memory")
#define TC_FENCE_AFTER()  asm volatile("tcgen05.fence::after_thread_sync;" ::: "memory")
#define TC_WAIT_LD()      asm volatile("tcgen05.wait::ld.sync.aligned;" ::: "memory")

__device__ __forceinline__ void mma_tf32_ss(uint32_t d, uint64_t a, uint64_t b,
                                            uint32_t idesc, uint32_t en) {
    asm volatile(
        "{\n\t.reg .pred p;\n\tsetp.ne.u32 p, %4, 0;\n\t"
        "tcgen05.mma.cta_group::1.kind::tf32 [%0], %1, %2, %3, p;\n\t}"
        :: "r"(d), "l"(a), "l"(b), "r"(idesc), "r"(en) : "memory");
}
#define LDTM_X16(r, addr) \
    asm volatile("tcgen05.ld.sync.aligned.32x32b.x16.b32 " \
        "{%0,%1,%2,%3,%4,%5,%6,%7,%8,%9,%10,%11,%12,%13,%14,%15}, [%16];" \
        : "=r"((r)[0]), "=r"((r)[1]), "=r"((r)[2]), "=r"((r)[3]), \
          "=r"((r)[4]), "=r"((r)[5]), "=r"((r)[6]), "=r"((r)[7]), \
          "=r"((r)[8]), "=r"((r)[9]), "=r"((r)[10]), "=r"((r)[11]), \
          "=r"((r)[12]), "=r"((r)[13]), "=r"((r)[14]), "=r"((r)[15]) \
        : "r"(addr))

__device__ __forceinline__ void tma2d(uint32_t dst, const void* map, int x, int y, uint32_t mbar) {
    asm volatile(
        "cp.async.bulk.tensor.2d.shared::cta.global.tile.mbarrier::complete_tx::bytes "
        "[%0], [%1, {%2, %3}], [%4];"
        :: "r"(dst), "l"(map), "r"(x), "r"(y), "r"(mbar) : "memory");
}
__device__ __forceinline__ uint64_t make_desc(uint32_t addr) {
    return (uint64_t(2) << 61) | (uint64_t(1) << 46) | (uint64_t(64) << 32)
         | (uint64_t(1) << 16) | ((uint64_t)(addr >> 4) & 0x3FFF);
}
// idesc: dtype=F32(1<<4), atype=TF32(2<<7), btype=TF32(2<<10), N=256, M=128
#define IDESC ((1u<<4) | (2u<<7) | (2u<<10) | ((NTT/8)<<17) | (8u<<24))
#endif // HAS_TCGEN05

extern __shared__ char dsmem[];

__global__ void __launch_bounds__(320, 1)
lstm_tc(const __grid_constant__ CUtensorMap tma_a,
        const __grid_constant__ CUtensorMap tma_b,
        const float* __restrict__ c0,
        const float* __restrict__ bii, const float* __restrict__ bif,
        const float* __restrict__ big, const float* __restrict__ bio,
        const float* __restrict__ bhi, const float* __restrict__ bhf,
        const float* __restrict__ bhg, const float* __restrict__ bho,
        float* __restrict__ out_h, float* __restrict__ out_c)
{
#if HAS_TCGEN05
    const uint32_t sb = smem_u32(dsmem);
    const uint32_t full0  = sb;        // 3 mbarriers
    const uint32_t empty0 = sb + 64;   // 3 mbarriers
    const uint32_t doneb  = sb + 128;
    const uint32_t tptr   = sb + 192;
    const uint32_t tiles  = (sb + 1024 + 1023) & ~1023u;

    const int tid = threadIdx.x;
    const int warp = tid >> 5;
    const int lane = tid & 31;
    const int m0    = blockIdx.y * MT2;     // batch-row base
    const int nrow0 = blockIdx.x * 256;     // g_W row base
    const int nh0   = blockIdx.x * 64;      // h-column base

    if (tid == 0) {
        #pragma unroll
        for (int s = 0; s < STAGES; s++) {
            MBAR_INIT(full0 + s * 8, 1);
            MBAR_INIT(empty0 + s * 8, 1);
        }
        MBAR_INIT(doneb, 1);
    }
    if (warp == 8) TC_ALLOC(tptr, 512);
    __syncthreads();

    uint32_t tmem;
    asm volatile("ld.shared.b32 %0, [%1];" : "=r"(tmem) : "r"(tptr));

    const int NKT = KTOT / KT;  // 128

    if (warp == 9 && lane == 0) {
        // ---------------- TMA producer ----------------
        int eph[STAGES] = {0, 0, 0};
        for (int kt = 0; kt < NKT; kt++) {
            const int s = kt % 3;
            if (kt >= STAGES) { MBAR_WAIT(empty0 + s * 8, eph[s]); eph[s] ^= 1; }
            const uint32_t a_dst = tiles + s * STAGE_BYTES;
            MBAR_EXPECT_TX(full0 + s * 8, STAGE_BYTES);
            tma2d(a_dst, &tma_a, kt * KT, m0, full0 + s * 8);
            tma2d(a_dst + A_STG, &tma_b, kt * KT, nrow0, full0 + s * 8);
        }
    } else if (warp == 8 && lane == 0) {
        // ---------------- MMA issuer ----------------
        uint64_t ad[STAGES], bd[STAGES];
        #pragma unroll
        for (int s = 0; s < STAGES; s++) {
            ad[s] = make_desc(tiles + s * STAGE_BYTES);
            bd[s] = make_desc(tiles + s * STAGE_BYTES + A_STG);
        }
        int ph[STAGES] = {0, 0, 0};
        for (int kt = 0; kt < NKT; kt++) {
            const int s = kt % 3;
            MBAR_WAIT(full0 + s * 8, ph[s]); ph[s] ^= 1;
            #pragma unroll
            for (int k = 0; k < KT / 8; k++) {
                const uint32_t en = (kt > 0 || k > 0) ? 1u : 0u;
                mma_tf32_ss(tmem,       ad[s] + k * 2,        bd[s] + k * 2, IDESC, en);
                mma_tf32_ss(tmem + 256, ad[s] + 1024 + k * 2, bd[s] + k * 2, IDESC, en);
            }
            TC_COMMIT((kt == NKT - 1) ? doneb : (empty0 + s * 8));
        }
    }

    // ---------------- epilogue: warps 0-7 ----------------
    if (warp < 8) {
        MBAR_WAIT(doneb, 0);
        TC_FENCE_AFTER();

        const int half = warp >> 2;            // 0: rows m0.., 1: rows m0+128..
        const int w4 = warp & 3;
        const int row = m0 + half * 128 + w4 * 32 + lane;
        const uint32_t tb = tmem + half * 256;
        const size_t rb = (size_t)row * HID + nh0;

        #pragma unroll
        for (int jc = 0; jc < 4; jc++) {
            uint32_t ri[16], rf[16], rg[16], ro[16];
            LDTM_X16(ri, tb + 0   + jc * 16);
            LDTM_X16(rf, tb + 64  + jc * 16);
            LDTM_X16(rg, tb + 128 + jc * 16);
            LDTM_X16(ro, tb + 192 + jc * 16);
            TC_WAIT_LD();
            #pragma unroll
            for (int e = 0; e < 16; e++) {
                const int col = nh0 + jc * 16 + e;
                const float gi = __uint_as_float(ri[e]) + __ldg(&bii[col]) + __ldg(&bhi[col]);
                const float gf = __uint_as_float(rf[e]) + __ldg(&bif[col]) + __ldg(&bhf[col]);
                const float gg = __uint_as_float(rg[e]) + __ldg(&big[col]) + __ldg(&bhg[col]);
                const float go = __uint_as_float(ro[e]) + __ldg(&bio[col]) + __ldg(&bho[col]);
                const float it = 1.f / (1.f + expf(-gi));
                const float ft = 1.f / (1.f + expf(-gf));
                const float gt = tanhf(gg);
                const float ot = 1.f / (1.f + expf(-go));
                const float cv = ft * __ldg(&c0[rb + jc * 16 + e]) + it * gt;
                out_h[rb + jc * 16 + e] = ot * tanhf(cv);
                out_c[rb + jc * 16 + e] = cv;
            }
        }
    }

    __syncthreads();
    if (warp == 8) {
        TC_RELINQ();
        TC_DEALLOC(tmem, 512);
    }
#endif // HAS_TCGEN05
}

// ======================================================================
// Fallback: legacy mma.sync tf32 kernel (known-good, 3413us)
// ======================================================================
#define FMT 128
#define FNT 32
#define FKT 32
#define SPAD 36
#define A_BUF_F (FMT * SPAD)
#define B_BUF_F (4 * FNT * SPAD)
#define B_BASE_F (2 * A_BUF_F)
#define FB_SMEM_BYTES ((2 * A_BUF_F + 2 * B_BUF_F) * (int)sizeof(float))

__device__ __forceinline__ void mma_tf32(float* d, const uint32_t* a, const uint32_t* b) {
    asm volatile(
        "mma.sync.aligned.m16n8k8.row.col.f32.tf32.tf32.f32 "
        "{%0,%1,%2,%3},{%4,%5,%6,%7},{%8,%9},{%0,%1,%2,%3};"
        : "+f"(d[0]), "+f"(d[1]), "+f"(d[2]), "+f"(d[3])
        : "r"(a[0]), "r"(a[1]), "r"(a[2]), "r"(a[3]), "r"(b[0]), "r"(b[1]));
}
__device__ __forceinline__ void cp16f(void* dst, const void* src) {
    uint32_t s = (uint32_t)__cvta_generic_to_shared(dst);
    asm volatile("cp.async.ca.shared.global [%0],[%1],16;" ::"r"(s), "l"(src));
}

__global__ void __launch_bounds__(256, 1)
lstm_fused_tf32(
    const float* __restrict__ x, const float* __restrict__ h0, const float* __restrict__ c0,
    const float* __restrict__ Wx0, const float* __restrict__ Wx1,
    const float* __restrict__ Wx2, const float* __restrict__ Wx3,
    const float* __restrict__ Wh0, const float* __restrict__ Wh1,
    const float* __restrict__ Wh2, const float* __restrict__ Wh3,
    const float* __restrict__ bx0, const float* __restrict__ bx1,
    const float* __restrict__ bx2, const float* __restrict__ bx3,
    const float* __restrict__ bh0, const float* __restrict__ bh1,
    const float* __restrict__ bh2, const float* __restrict__ bh3,
    float* __restrict__ out_h, float* __restrict__ out_c)
{
    float* smem = (float*)dsmem;
    const int t = threadIdx.x;
    const int m_base = blockIdx.y * FMT;
    const int n_base = blockIdx.x * FNT;

    const float* Wx[4] = {Wx0, Wx1, Wx2, Wx3};
    const float* Wh[4] = {Wh0, Wh1, Wh2, Wh3};

    const int lrow = t >> 3;
    const int lc4  = (t & 7) * 4;

    auto load_tile = [&](int buf, int kt) {
        const int k0 = kt * FKT;
        const bool first = (k0 < 2048);
        const float* Asrc = first ? x : h0;
        const int kofs = first ? k0 : (k0 - 2048);
        #pragma unroll
        for (int i = 0; i < 4; i++) {
            int r = i * 32 + lrow;
            cp16f(&smem[buf * A_BUF_F + r * SPAD + lc4],
                  Asrc + (size_t)(m_base + r) * 2048 + kofs + lc4);
        }
        #pragma unroll
        for (int g = 0; g < 4; g++) {
            const float* W = first ? Wx[g] : Wh[g];
            cp16f(&smem[B_BASE_F + buf * B_BUF_F + g * (FNT * SPAD) + lrow * SPAD + lc4],
                  W + (size_t)(n_base + lrow) * 2048 + kofs + lc4);
        }
        asm volatile("cp.async.commit_group;");
    };

    const int warp = t >> 5;
    const int lane = t & 31;
    const int wm = warp & 3;
    const int wn = warp >> 2;
    const int gid = lane >> 2;
    const int tig = lane & 3;

    float acc[4][2][2][4];
    #pragma unroll
    for (int g = 0; g < 4; g++)
        #pragma unroll
        for (int mi = 0; mi < 2; mi++)
            #pragma unroll
            for (int ni = 0; ni < 2; ni++)
                #pragma unroll
                for (int e = 0; e < 4; e++) acc[g][mi][ni][e] = 0.f;

    const int NKT = KTOT / FKT;
    int buf = 0;
    load_tile(0, 0);

    for (int kt = 0; kt < NKT; kt++) {
        asm volatile("cp.async.wait_group 0;");
        __syncthreads();
        if (kt + 1 < NKT) load_tile(buf ^ 1, kt + 1);

        const float* As = &smem[buf * A_BUF_F];
        const float* Bs = &smem[B_BASE_F + buf * B_BUF_F];

        #pragma unroll
        for (int kk = 0; kk < FKT / 8; kk++) {
            const int kb = kk * 8;
            uint32_t a[2][4];
            #pragma unroll
            for (int mi = 0; mi < 2; mi++) {
                const float* Ab = As + (wm * 32 + mi * 16 + gid) * SPAD + kb + tig;
                a[mi][0] = f2tf32(Ab[0]);
                a[mi][1] = f2tf32(Ab[8 * SPAD]);
                a[mi][2] = f2tf32(Ab[4]);
                a[mi][3] = f2tf32(Ab[8 * SPAD + 4]);
            }
            uint32_t bfr[4][2][2];
            #pragma unroll
            for (int g = 0; g < 4; g++) {
                #pragma unroll
                for (int ni = 0; ni < 2; ni++) {
                    const float* Bb = Bs + g * (FNT * SPAD) + (wn * 16 + ni * 8 + gid) * SPAD + kb + tig;
                    bfr[g][ni][0] = f2tf32(Bb[0]);
                    bfr[g][ni][1] = f2tf32(Bb[4]);
                }
            }
            #pragma unroll
            for (int g = 0; g < 4; g++)
                #pragma unroll
                for (int mi = 0; mi < 2; mi++)
                    #pragma unroll
                    for (int ni = 0; ni < 2; ni++)
                        mma_tf32(acc[g][mi][ni], a[mi], bfr[g][ni]);
        }
        __syncthreads();
        buf ^= 1;
    }

    const int mrow = m_base + wm * 32;
    const int ncol = n_base + wn * 16;
    #pragma unroll
    for (int mi = 0; mi < 2; mi++) {
        #pragma unroll
        for (int ni = 0; ni < 2; ni++) {
            #pragma unroll
            for (int half = 0; half < 2; half++) {
                const int col = ncol + ni * 8 + tig * 2 + half;
                const float bi = __ldg(&bx0[col]) + __ldg(&bh0[col]);
                const float bf = __ldg(&bx1[col]) + __ldg(&bh1[col]);
                const float bg = __ldg(&bx2[col]) + __ldg(&bh2[col]);
                const float bo = __ldg(&bx3[col]) + __ldg(&bh3[col]);
                #pragma unroll
                for (int rh = 0; rh < 2; rh++) {
                    const int row = mrow + mi * 16 + gid + rh * 8;
                    const int e = rh * 2 + half;
                    const float gi = acc[0][mi][ni][e] + bi;
                    const float gf = acc[1][mi][ni][e] + bf;
                    const float gg = acc[2][mi][ni][e] + bg;
                    const float go = acc[3][mi][ni][e] + bo;
                    const float it = 1.f / (1.f + expf(-gi));
                    const float ft = 1.f / (1.f + expf(-gf));
                    const float gt = tanhf(gg);
                    const float ot = 1.f / (1.f + expf(-go));
                    const size_t off = (size_t)row * HID + col;
                    const float cv = ft * __ldg(&c0[off]) + it * gt;
                    out_h[off] = ot * tanhf(cv);
                    out_c[off] = cv;
                }
            }
        }
    }
}

// ============================ launch ============================
typedef CUresult (*tmap_encode_fn)(
    CUtensorMap*, CUtensorMapDataType, cuuint32_t, void*,
    const cuuint64_t*, const cuuint64_t*, const cuuint32_t*, const cuuint32_t*,
    CUtensorMapInterleave, CUtensorMapSwizzle, CUtensorMapL2promotion,
    CUtensorMapFloatOOBfill);

extern "C" void kernel_launch(void* const* d_in, const int* in_sizes, int n_in,
                              void* d_out, int out_size) {
    const float* x   = (const float*)d_in[0];
    const float* h0  = (const float*)d_in[1];
    const float* c0  = (const float*)d_in[2];
    const float* Wii = (const float*)d_in[3];  const float* bii = (const float*)d_in[4];
    const float* Wif = (const float*)d_in[5];  const float* bif = (const float*)d_in[6];
    const float* Wig = (const float*)d_in[7];  const float* big = (const float*)d_in[8];
    const float* Wio = (const float*)d_in[9];  const float* bio = (const float*)d_in[10];
    const float* Whi = (const float*)d_in[11]; const float* bhi = (const float*)d_in[12];
    const float* Whf = (const float*)d_in[13]; const float* bhf = (const float*)d_in[14];
    const float* Whg = (const float*)d_in[15]; const float* bhg = (const float*)d_in[16];
    const float* Who = (const float*)d_in[17]; const float* bho = (const float*)d_in[18];

    float* out_h = (float*)d_out;
    float* out_c = out_h + (size_t)BATCH * HID;

    static int use_tc = -1;
    static CUtensorMap tmapA, tmapB;
    if (use_tc < 0) {
        use_tc = 0;
        cudaFuncAttributes attr;
        if (cudaFuncGetAttributes(&attr, lstm_tc) == cudaSuccess && attr.numRegs > 32) {
            void* fn = nullptr;
            cudaDriverEntryPointQueryResult qres;
            if (cudaGetDriverEntryPoint("cuTensorMapEncodeTiled", &fn,
                                        cudaEnableDefault, &qres) == cudaSuccess && fn) {
                void *pA = nullptr, *pW = nullptr;
                cudaGetSymbolAddress(&pA, g_A);
                cudaGetSymbolAddress(&pW, g_W);
                cuuint64_t dims[2] = {KTOT, 8192};
                cuuint64_t strides[1] = {(cuuint64_t)KTOT * 4};
                cuuint32_t box[2] = {32, 256};
                cuuint32_t es[2] = {1, 1};
                tmap_encode_fn enc = (tmap_encode_fn)fn;
                CUresult r1 = enc(&tmapA, CU_TENSOR_MAP_DATA_TYPE_FLOAT32, 2, pA,
                                  dims, strides, box, es,
                                  CU_TENSOR_MAP_INTERLEAVE_NONE,
                                  CU_TENSOR_MAP_SWIZZLE_128B,
                                  CU_TENSOR_MAP_L2_PROMOTION_L2_128B,
                                  CU_TENSOR_MAP_FLOAT_OOB_FILL_NONE);
                CUresult r2 = enc(&tmapB, CU_TENSOR_MAP_DATA_TYPE_FLOAT32, 2, pW,
                                  dims, strides, box, es,
                                  CU_TENSOR_MAP_INTERLEAVE_NONE,
                                  CU_TENSOR_MAP_SWIZZLE_128B,
                                  CU_TENSOR_MAP_L2_PROMOTION_L2_128B,
                                  CU_TENSOR_MAP_FLOAT_OOB_FILL_NONE);
                if (r1 == CUDA_SUCCESS && r2 == CUDA_SUCCESS && pA && pW)
                    use_tc = 1;
            }
        }
        if (use_tc) {
            cudaFuncSetAttribute(lstm_tc, cudaFuncAttributeMaxDynamicSharedMemorySize,
                                 TC_SMEM_BYTES);
        } else {
            cudaFuncSetAttribute(lstm_fused_tf32,
                                 cudaFuncAttributeMaxDynamicSharedMemorySize, FB_SMEM_BYTES);
        }
    }

    if (use_tc) {
        pack_a<<<4096, 256>>>(x, h0);
        pack_w<<<4096, 256>>>(Wii, Wif, Wig, Wio, Whi, Whf, Whg, Who);
        dim3 grid(HID / 64, BATCH / MT2);   // (32, 32)
        lstm_tc<<<grid, 320, TC_SMEM_BYTES>>>(tmapA, tmapB, c0,
            bii, bif, big, bio, bhi, bhf, bhg, bho, out_h, out_c);
    } else {
        dim3 grid(HID / FNT, BATCH / FMT);  // (64, 64)
        lstm_fused_tf32<<<grid, 256, FB_SMEM_BYTES>>>(
            x, h0, c0,
            Wii, Wif, Wig, Wio,
            Whi, Whf, Whg, Who,
            bii, bif, big, bio,
            bhi, bhf, bhg, bho,
            out_h, out_c);
    }
}